// round 1
// baseline (speedup 1.0000x reference)
#include <cuda_runtime.h>
#include <math.h>

#define N_NODES 25000
#define N_EDGES 250000
#define DIM 64
#define HEADS 4
#define C 256            // HEADS*DIM
#define EB 8             // edges per tile

// Scratch (static device allocations are allowed)
__device__ float g_P[N_NODES * C];        // x @ W_top      (25.6 MB, L2-resident)
__device__ float g_outj[(size_t)N_EDGES * C]; // softplus(P_j + q)  (256 MB)
__device__ float g_expv[N_EDGES * HEADS];
__device__ float g_denom[N_NODES * HEADS];

__device__ __forceinline__ float sp(float x) {
    // softplus = max(x,0) + log1p(exp(-|x|)); fast-math variant is plenty for 1e-3
    return fmaxf(x, 0.f) + __logf(1.f + __expf(-fabsf(x)));
}

__global__ void k_init(const float* __restrict__ bias, float* __restrict__ out) {
    int i = blockIdx.x * blockDim.x + threadIdx.x;
    if (i < N_NODES * DIM) out[i] = bias[i & 63];
    if (i < N_NODES * HEADS) g_denom[i] = 0.f;
}

// P[n, t] = sum_k x[n,k] * W[k, t]   (W_top = first 64 rows of W)
__global__ void __launch_bounds__(256, 2) k_P(const float* __restrict__ x,
                                              const float* __restrict__ W) {
    int t = threadIdx.x;
    float wcol[DIM];
#pragma unroll
    for (int k = 0; k < DIM; k++) wcol[k] = W[k * C + t];
    __shared__ float sx[DIM];
    for (int n = blockIdx.x; n < N_NODES; n += gridDim.x) {
        __syncthreads();
        if (t < 16) ((float4*)sx)[t] = ((const float4*)(x + n * DIM))[t];
        __syncthreads();
        float acc = 0.f;
#pragma unroll
        for (int k = 0; k < DIM; k++) acc = fmaf(sx[k], wcol[k], acc);
        g_P[n * C + t] = acc;
    }
}

// Per-edge pass: q = ea @ W_bot ; out_i/out_j ; attention logits ; exp ; denom atomics
__global__ void __launch_bounds__(256, 2) k_edge(
    const float* __restrict__ edge_attr, const float* __restrict__ W,
    const float* __restrict__ att, const float* __restrict__ bn_g,
    const float* __restrict__ bn_b, const float* __restrict__ bn_m,
    const float* __restrict__ bn_v, const int* __restrict__ ei) {
    int t = threadIdx.x;
    int h = t >> 6, d = t & 63;
    int warp = t >> 5, lane = t & 31;
    float wcol[DIM];
#pragma unroll
    for (int k = 0; k < DIM; k++) wcol[k] = W[(DIM + k) * C + t];
    const float ai = att[h * 128 + d];
    const float aj = att[h * 128 + 64 + d];

    __shared__ float sea[EB][DIM];
    __shared__ int   sii[EB], sjj[EB];
    __shared__ float sred[EB][8];

    const int* idx_i = ei;
    const int* idx_j = ei + N_EDGES;

    for (int base = blockIdx.x * EB; base < N_EDGES; base += gridDim.x * EB) {
        __syncthreads();
        if (t < 128) {  // EB*64 floats = 128 float4
            int ee = t >> 4, q4 = t & 15;
            ((float4*)sea[ee])[q4] =
                ((const float4*)(edge_attr + (size_t)(base + ee) * DIM))[q4];
        } else if (t < 128 + EB) {
            int ee = t - 128;
            sii[ee] = idx_i[base + ee];
            sjj[ee] = idx_j[base + ee];
        }
        __syncthreads();
#pragma unroll 1
        for (int ee = 0; ee < EB; ee++) {
            float q = 0.f;
#pragma unroll
            for (int k = 0; k < DIM; k++) q = fmaf(sea[ee][k], wcol[k], q);
            int ni = sii[ee], nj = sjj[ee];
            float oi = sp(g_P[ni * C + t] + q);
            float oj = sp(g_P[nj * C + t] + q);
            g_outj[(size_t)(base + ee) * C + t] = oj;
            float partial = oi * ai + oj * aj;
#pragma unroll
            for (int off = 16; off; off >>= 1)
                partial += __shfl_xor_sync(0xffffffffu, partial, off);
            if (lane == 0) sred[ee][warp] = partial;
        }
        __syncthreads();
        if (t < EB * HEADS) {
            int ee = t >> 2, hh = t & 3;
            float s = sred[ee][hh * 2] + sred[ee][hh * 2 + 1];
            float a = sp(s);
            a = sp((a - bn_m[hh]) * rsqrtf(bn_v[hh] + 1e-5f) * bn_g[hh] + bn_b[hh]);
            float ex = __expf(a);      // no max-subtract needed: a in [0, ~3]
            g_expv[(base + ee) * HEADS + hh] = ex;
            atomicAdd(&g_denom[sii[ee] * HEADS + hh], ex);
        }
    }
}

// Aggregation: out[i,d] += 0.25 * sum_h (exp/denom) * out_j[e, h*64+d]
__global__ void __launch_bounds__(256, 4) k_aggr(const int* __restrict__ ei,
                                                 float* __restrict__ out) {
    int t = threadIdx.x;
    const int* idx_i = ei;
    __shared__ float sc[EB][C];
    __shared__ float sw[EB][HEADS];
    __shared__ int   sii[EB];

    for (int base = blockIdx.x * EB; base < N_EDGES; base += gridDim.x * EB) {
        __syncthreads();
        if (t < EB) sii[t] = idx_i[base + t];
        __syncthreads();
        if (t < EB * HEADS) {
            int ee = t >> 2, hh = t & 3;
            float ex = g_expv[(base + ee) * HEADS + hh];
            float dn = g_denom[sii[ee] * HEADS + hh];
            sw[ee][hh] = 0.25f * ex / dn;
        }
        __syncthreads();
#pragma unroll 1
        for (int ee = 0; ee < EB; ee++) {
            float oj = g_outj[(size_t)(base + ee) * C + t];
            sc[ee][t] = oj * sw[ee][t >> 6];
        }
        __syncthreads();
#pragma unroll
        for (int r = 0; r < 2; r++) {
            int p = t + r * 256;            // 512 (edge,d) pairs
            int ee = p >> 6, d = p & 63;
            float v = sc[ee][d] + sc[ee][64 + d] + sc[ee][128 + d] + sc[ee][192 + d];
            atomicAdd(&out[sii[ee] * DIM + d], v);
        }
    }
}

extern "C" void kernel_launch(void* const* d_in, const int* in_sizes, int n_in,
                              void* d_out, int out_size) {
    const float* x        = (const float*)d_in[0];
    const float* edge_attr= (const float*)d_in[1];
    const float* W        = (const float*)d_in[2];
    const float* att      = (const float*)d_in[3];
    const float* bias     = (const float*)d_in[4];
    const float* bn_g     = (const float*)d_in[5];
    const float* bn_b     = (const float*)d_in[6];
    const float* bn_m     = (const float*)d_in[7];
    const float* bn_v     = (const float*)d_in[8];
    const int*   ei       = (const int*)d_in[9];
    float* out = (float*)d_out;

    k_init<<<(N_NODES * DIM + 255) / 256, 256>>>(bias, out);
    k_P<<<296, 256>>>(x, W);
    k_edge<<<1184, 256>>>(edge_attr, W, att, bn_g, bn_b, bn_m, bn_v, ei);
    k_aggr<<<1184, 256>>>(ei, out);
}

// round 2
// speedup vs baseline: 1.1184x; 1.1184x over previous
#include <cuda_runtime.h>
#include <math.h>

#define N_NODES 25000
#define N_EDGES 250000
#define DIM 64
#define HEADS 4
#define C 256            // HEADS*DIM
#define EB 8             // edges per tile

// Scratch
__device__ float g_P[N_NODES * C];                       // x @ W_top (25.6 MB, L2-resident)
__device__ __align__(16) float g_num[N_NODES * C];       // unnormalized aggregation
__device__ float g_denom[N_NODES * HEADS];

__device__ __forceinline__ float sp(float x) {
    return fmaxf(x, 0.f) + __logf(1.f + __expf(-fabsf(x)));
}

__device__ __forceinline__ unsigned long long pk2(float a, float b) {
    unsigned long long r;
    asm("mov.b64 %0, {%1, %2};" : "=l"(r) : "f"(a), "f"(b));
    return r;
}
__device__ __forceinline__ void ffma2(unsigned long long& acc,
                                      unsigned long long a, unsigned long long b) {
    asm("fma.rn.f32x2 %0, %1, %2, %0;" : "+l"(acc) : "l"(a), "l"(b));
}
__device__ __forceinline__ float2 unpk2(unsigned long long v) {
    float2 f;
    asm("mov.b64 {%0, %1}, %2;" : "=f"(f.x), "=f"(f.y) : "l"(v));
    return f;
}

__global__ void k_init() {
    int i = blockIdx.x * blockDim.x + threadIdx.x;
    if (i < N_NODES * C) g_num[i] = 0.f;
    if (i < N_NODES * HEADS) g_denom[i] = 0.f;
}

// P[n, t] = sum_k x[n,k] * W[k, t]   (W_top = first 64 rows of W)
__global__ void __launch_bounds__(256, 2) k_P(const float* __restrict__ x,
                                              const float* __restrict__ W) {
    int t = threadIdx.x;
    unsigned long long w2[DIM / 2];
#pragma unroll
    for (int k = 0; k < DIM / 2; k++) w2[k] = pk2(W[(2 * k) * C + t], W[(2 * k + 1) * C + t]);
    __shared__ float4 sx[DIM / 4];
    for (int n = blockIdx.x; n < N_NODES; n += gridDim.x) {
        __syncthreads();
        if (t < 16) sx[t] = ((const float4*)(x + n * DIM))[t];
        __syncthreads();
        unsigned long long a0 = 0ull, a1 = 0ull;
#pragma unroll
        for (int k4 = 0; k4 < 16; k4 += 2) {
            float4 e0 = sx[k4], e1 = sx[k4 + 1];
            ffma2(a0, pk2(e0.x, e0.y), w2[2 * k4]);
            ffma2(a1, pk2(e0.z, e0.w), w2[2 * k4 + 1]);
            ffma2(a0, pk2(e1.x, e1.y), w2[2 * k4 + 2]);
            ffma2(a1, pk2(e1.z, e1.w), w2[2 * k4 + 3]);
        }
        float2 f0 = unpk2(a0), f1 = unpk2(a1);
        g_P[n * C + t] = (f0.x + f0.y) + (f1.x + f1.y);
    }
}

// Fused edge pass: q = ea@W_bot ; oi/oj ; logits ; BN ; exp ; unnormalized scatter
__global__ void __launch_bounds__(256, 2) k_edge(
    const float* __restrict__ edge_attr, const float* __restrict__ W,
    const float* __restrict__ att, const float* __restrict__ bn_g,
    const float* __restrict__ bn_b, const float* __restrict__ bn_m,
    const float* __restrict__ bn_v, const int* __restrict__ ei) {
    int t = threadIdx.x;
    int h = t >> 6, d = t & 63;
    int warp = t >> 5, lane = t & 31;

    unsigned long long w2[DIM / 2];
#pragma unroll
    for (int k = 0; k < DIM / 2; k++)
        w2[k] = pk2(W[(DIM + 2 * k) * C + t], W[(DIM + 2 * k + 1) * C + t]);
    const float ai = att[h * 128 + d];
    const float aj = att[h * 128 + 64 + d];

    __shared__ float4 sea[EB][DIM / 4];
    __shared__ int    sii[EB], sjj[EB];
    __shared__ float  sred[EB][8];
    __shared__ float  sexp[EB][HEADS];
    __shared__ float  sbn[2][HEADS];       // scale, shift
    __shared__ __align__(16) float sc[EB][C];

    if (t < HEADS) {
        float s = bn_g[t] * rsqrtf(bn_v[t] + 1e-5f);
        sbn[0][t] = s;
        sbn[1][t] = bn_b[t] - bn_m[t] * s;
    }

    const int* idx_i = ei;
    const int* idx_j = ei + N_EDGES;

    for (int base = blockIdx.x * EB; base < N_EDGES; base += gridDim.x * EB) {
        __syncthreads();
        if (t < 128) {                       // EB*16 float4s
            int ee = t >> 4, q4 = t & 15;
            sea[ee][q4] = ((const float4*)(edge_attr + (size_t)(base + ee) * DIM))[q4];
        } else if (t < 128 + EB) {
            int ee = t - 128;
            sii[ee] = idx_i[base + ee];
            sjj[ee] = idx_j[base + ee];
        }
        __syncthreads();

        float oj_r[EB];
#pragma unroll 1
        for (int ee = 0; ee < EB; ee++) {
            unsigned long long a0 = 0ull, a1 = 0ull;
#pragma unroll
            for (int k4 = 0; k4 < 16; k4++) {
                float4 e = sea[ee][k4];
                ffma2(a0, pk2(e.x, e.y), w2[2 * k4]);
                ffma2(a1, pk2(e.z, e.w), w2[2 * k4 + 1]);
            }
            float2 f0 = unpk2(a0), f1 = unpk2(a1);
            float q = (f0.x + f0.y) + (f1.x + f1.y);
            float oi = sp(g_P[sii[ee] * C + t] + q);
            float oj = sp(g_P[sjj[ee] * C + t] + q);
            oj_r[ee] = oj;
            float partial = oi * ai + oj * aj;
#pragma unroll
            for (int off = 16; off; off >>= 1)
                partial += __shfl_xor_sync(0xffffffffu, partial, off);
            if (lane == 0) sred[ee][warp] = partial;
        }
        __syncthreads();
        if (t < EB * HEADS) {
            int ee = t >> 2, hh = t & 3;
            float a = sp(sred[ee][hh * 2] + sred[ee][hh * 2 + 1]);
            a = sp(a * sbn[0][hh] + sbn[1][hh]);
            float ex = __expf(a);            // logits bounded: no max-subtract needed
            sexp[ee][hh] = ex;
            atomicAdd(&g_denom[sii[ee] * HEADS + hh], ex);
        }
        __syncthreads();
#pragma unroll
        for (int ee = 0; ee < EB; ee++)
            sc[ee][t] = oj_r[ee] * sexp[ee][h];
        __syncthreads();
#pragma unroll
        for (int r = 0; r < 2; r++) {
            int p = t + r * 256;             // 512 quads: 8 edges x 64 quads
            int ee = p >> 6, qd = p & 63;
            const float4 v = *(const float4*)&sc[ee][qd * 4];
            float* dst = &g_num[(size_t)sii[ee] * C + qd * 4];
            asm volatile("red.global.add.v4.f32 [%0], {%1, %2, %3, %4};"
                         :: "l"(dst), "f"(v.x), "f"(v.y), "f"(v.z), "f"(v.w)
                         : "memory");
        }
    }
}

// out[n,d] = bias[d] + 0.25 * sum_h num[n,h,d] / denom[n,h]
__global__ void k_final(const float* __restrict__ bias, float* __restrict__ out) {
    int i = blockIdx.x * blockDim.x + threadIdx.x;
    if (i >= N_NODES * DIM) return;
    int n = i >> 6, d = i & 63;
    float acc = 0.f;
#pragma unroll
    for (int hh = 0; hh < HEADS; hh++) {
        float dn = g_denom[n * HEADS + hh];
        float nm = g_num[n * C + hh * DIM + d];
        acc += (dn > 0.f) ? nm / dn : 0.f;
    }
    out[i] = 0.25f * acc + bias[d];
}

extern "C" void kernel_launch(void* const* d_in, const int* in_sizes, int n_in,
                              void* d_out, int out_size) {
    const float* x         = (const float*)d_in[0];
    const float* edge_attr = (const float*)d_in[1];
    const float* W         = (const float*)d_in[2];
    const float* att       = (const float*)d_in[3];
    const float* bias      = (const float*)d_in[4];
    const float* bn_g      = (const float*)d_in[5];
    const float* bn_b      = (const float*)d_in[6];
    const float* bn_m      = (const float*)d_in[7];
    const float* bn_v      = (const float*)d_in[8];
    const int*   ei        = (const int*)d_in[9];
    float* out = (float*)d_out;

    k_init<<<(N_NODES * C + 255) / 256, 256>>>();
    k_P<<<592, 256>>>(x, W);
    k_edge<<<1184, 256>>>(edge_attr, W, att, bn_g, bn_b, bn_m, bn_v, ei);
    k_final<<<(N_NODES * DIM + 255) / 256, 256>>>(bias, out);
}

// round 5
// speedup vs baseline: 1.1205x; 1.0019x over previous
#include <cuda_runtime.h>
#include <math.h>

#define N_NODES 25000
#define N_EDGES 250000
#define DIM 64
#define HEADS 4
#define C 256            // HEADS*DIM
#define EB 8             // edges per tile

// Scratch
__device__ float g_P[N_NODES * C];                       // x @ W_top (25.6 MB, L2-resident)
__device__ __align__(16) float g_num[N_NODES * C];       // unnormalized aggregation
__device__ float g_denom[N_NODES * HEADS];

__device__ __forceinline__ float sp(float x) {
    return fmaxf(x, 0.f) + __logf(1.f + __expf(-fabsf(x)));
}

__device__ __forceinline__ unsigned long long pk2(float a, float b) {
    unsigned long long r;
    asm("mov.b64 %0, {%1, %2};" : "=l"(r) : "f"(a), "f"(b));
    return r;
}
__device__ __forceinline__ void ffma2(unsigned long long& acc,
                                      unsigned long long a, unsigned long long b) {
    asm("fma.rn.f32x2 %0, %1, %2, %0;" : "+l"(acc) : "l"(a), "l"(b));
}
__device__ __forceinline__ float2 unpk2(unsigned long long v) {
    float2 f;
    asm("mov.b64 {%0, %1}, %2;" : "=f"(f.x), "=f"(f.y) : "l"(v));
    return f;
}

__global__ void k_init() {
    int i = blockIdx.x * blockDim.x + threadIdx.x;
    if (i < N_NODES * C) g_num[i] = 0.f;
    if (i < N_NODES * HEADS) g_denom[i] = 0.f;
}

// P[n, t] = sum_k x[n,k] * W[k, t]   (W_top = first 64 rows of W)
__global__ void __launch_bounds__(256, 2) k_P(const float* __restrict__ x,
                                              const float* __restrict__ W) {
    int t = threadIdx.x;
    unsigned long long w2[DIM / 2];
#pragma unroll
    for (int k = 0; k < DIM / 2; k++) w2[k] = pk2(W[(2 * k) * C + t], W[(2 * k + 1) * C + t]);
    __shared__ float4 sx[DIM / 4];
    for (int n = blockIdx.x; n < N_NODES; n += gridDim.x) {
        __syncthreads();
        if (t < 16) sx[t] = ((const float4*)(x + n * DIM))[t];
        __syncthreads();
        unsigned long long a0 = 0ull, a1 = 0ull;
#pragma unroll
        for (int k4 = 0; k4 < 16; k4 += 2) {
            float4 e0 = sx[k4], e1 = sx[k4 + 1];
            ffma2(a0, pk2(e0.x, e0.y), w2[2 * k4]);
            ffma2(a1, pk2(e0.z, e0.w), w2[2 * k4 + 1]);
            ffma2(a0, pk2(e1.x, e1.y), w2[2 * k4 + 2]);
            ffma2(a1, pk2(e1.z, e1.w), w2[2 * k4 + 3]);
        }
        float2 f0 = unpk2(a0), f1 = unpk2(a1);
        g_P[n * C + t] = (f0.x + f0.y) + (f1.x + f1.y);
    }
}

// Fused edge pass: q = ea@W_bot ; oi/oj ; logits ; BN ; exp ; unnormalized scatter
__global__ void __launch_bounds__(256, 2) k_edge(
    const float* __restrict__ edge_attr, const float* __restrict__ W,
    const float* __restrict__ att, const float* __restrict__ bn_g,
    const float* __restrict__ bn_b, const float* __restrict__ bn_m,
    const float* __restrict__ bn_v, const int* __restrict__ ei) {
    int t = threadIdx.x;
    int h = t >> 6, d = t & 63;
    int warp = t >> 5, lane = t & 31;

    unsigned long long w2[DIM / 2];
#pragma unroll
    for (int k = 0; k < DIM / 2; k++)
        w2[k] = pk2(W[(DIM + 2 * k) * C + t], W[(DIM + 2 * k + 1) * C + t]);
    const float ai = att[h * 128 + d];
    const float aj = att[h * 128 + 64 + d];

    __shared__ float4 sea[EB][DIM / 4];
    __shared__ int    sii[EB], sjj[EB];
    __shared__ float  sred[EB][8];
    __shared__ float  sexp[EB][HEADS];
    __shared__ float  sbn[2][HEADS];       // scale, shift
    __shared__ __align__(16) float sc[EB][C];

    if (t < HEADS) {
        float s = bn_g[t] * rsqrtf(bn_v[t] + 1e-5f);
        sbn[0][t] = s;
        sbn[1][t] = bn_b[t] - bn_m[t] * s;
    }

    const int* idx_i = ei;
    const int* idx_j = ei + N_EDGES;

    for (int base = blockIdx.x * EB; base < N_EDGES; base += gridDim.x * EB) {
        __syncthreads();
        if (t < 128) {                       // EB*16 float4s
            int ee = t >> 4, q4 = t & 15;
            sea[ee][q4] = ((const float4*)(edge_attr + (size_t)(base + ee) * DIM))[q4];
        } else if (t < 128 + EB) {
            int ee = t - 128;
            sii[ee] = idx_i[base + ee];
            sjj[ee] = idx_j[base + ee];
        }
        __syncthreads();

        // Phase 0: prefetch all 16 gathers (independent -> MLP 16)
        float pi[EB], pj[EB];
#pragma unroll
        for (int ee = 0; ee < EB; ee++) {
            pi[ee] = __ldg(&g_P[sii[ee] * C + t]);
            pj[ee] = __ldg(&g_P[sjj[ee] * C + t]);
        }

        // Phase 1: matvec + softplus; keep per-edge partial logits in registers
        float oj_r[EB], part[EB];
#pragma unroll 1
        for (int ee = 0; ee < EB; ee++) {
            unsigned long long a0 = 0ull, a1 = 0ull;
#pragma unroll
            for (int k4 = 0; k4 < 16; k4++) {
                float4 e = sea[ee][k4];
                ffma2(a0, pk2(e.x, e.y), w2[2 * k4]);
                ffma2(a1, pk2(e.z, e.w), w2[2 * k4 + 1]);
            }
            float2 f0 = unpk2(a0), f1 = unpk2(a1);
            float q = (f0.x + f0.y) + (f1.x + f1.y);
            float oi = sp(pi[ee] + q);
            float oj = sp(pj[ee] + q);
            oj_r[ee] = oj;
            part[ee] = oi * ai + oj * aj;
        }

        // Phase 2: 8 independent butterfly chains, interleaved (latency overlapped)
#pragma unroll
        for (int off = 16; off; off >>= 1) {
#pragma unroll
            for (int ee = 0; ee < EB; ee++)
                part[ee] += __shfl_xor_sync(0xffffffffu, part[ee], off);
        }
        if (lane == 0) {
#pragma unroll
            for (int ee = 0; ee < EB; ee++) sred[ee][warp] = part[ee];
        }
        __syncthreads();
        if (t < EB * HEADS) {
            int ee = t >> 2, hh = t & 3;
            float a = sp(sred[ee][hh * 2] + sred[ee][hh * 2 + 1]);
            a = sp(a * sbn[0][hh] + sbn[1][hh]);
            float ex = __expf(a);            // logits bounded: no max-subtract needed
            sexp[ee][hh] = ex;
            atomicAdd(&g_denom[sii[ee] * HEADS + hh], ex);
        }
        __syncthreads();
#pragma unroll
        for (int ee = 0; ee < EB; ee++)
            sc[ee][t] = oj_r[ee] * sexp[ee][h];
        __syncthreads();
#pragma unroll
        for (int r = 0; r < 2; r++) {
            int p = t + r * 256;             // 512 quads: 8 edges x 64 quads
            int ee = p >> 6, qd = p & 63;
            const float4 v = *(const float4*)&sc[ee][qd * 4];
            float* dst = &g_num[(size_t)sii[ee] * C + qd * 4];
            asm volatile("red.global.add.v4.f32 [%0], {%1, %2, %3, %4};"
                         :: "l"(dst), "f"(v.x), "f"(v.y), "f"(v.z), "f"(v.w)
                         : "memory");
        }
    }
}

// out[n, q4] = bias + 0.25 * sum_h num[n,h,q4] / denom[n,h]   (float4 per thread)
__global__ void k_final(const float* __restrict__ bias, float* __restrict__ out) {
    int i = blockIdx.x * blockDim.x + threadIdx.x;   // N_NODES*16 quads
    if (i >= N_NODES * 16) return;
    int n = i >> 4, q = i & 15;
    float inv[HEADS];
#pragma unroll
    for (int hh = 0; hh < HEADS; hh++) {
        float dn = g_denom[n * HEADS + hh];
        inv[hh] = (dn > 0.f) ? 0.25f / dn : 0.f;
    }
    float4 acc = make_float4(0.f, 0.f, 0.f, 0.f);
#pragma unroll
    for (int hh = 0; hh < HEADS; hh++) {
        float4 v = *(const float4*)&g_num[n * C + hh * DIM + q * 4];
        acc.x += v.x * inv[hh]; acc.y += v.y * inv[hh];
        acc.z += v.z * inv[hh]; acc.w += v.w * inv[hh];
    }
    float4 b = *(const float4*)&bias[q * 4];
    acc.x += b.x; acc.y += b.y; acc.z += b.z; acc.w += b.w;
    *(float4*)&out[n * DIM + q * 4] = acc;
}

extern "C" void kernel_launch(void* const* d_in, const int* in_sizes, int n_in,
                              void* d_out, int out_size) {
    const float* x         = (const float*)d_in[0];
    const float* edge_attr = (const float*)d_in[1];
    const float* W         = (const float*)d_in[2];
    const float* att       = (const float*)d_in[3];
    const float* bias      = (const float*)d_in[4];
    const float* bn_g      = (const float*)d_in[5];
    const float* bn_b      = (const float*)d_in[6];
    const float* bn_m      = (const float*)d_in[7];
    const float* bn_v      = (const float*)d_in[8];
    const int*   ei        = (const int*)d_in[9];
    float* out = (float*)d_out;

    k_init<<<(N_NODES * C + 255) / 256, 256>>>();
    k_P<<<592, 256>>>(x, W);
    k_edge<<<1184, 256>>>(edge_attr, W, att, bn_g, bn_b, bn_m, bn_v, ei);
    k_final<<<(N_NODES * 16 + 255) / 256, 256>>>(bias, out);
}